// round 4
// baseline (speedup 1.0000x reference)
#include <cuda_runtime.h>

#define B_   2
#define C_   64
#define H_   192
#define W_   192
#define HW_  (H_*W_)
#define O_   64
#define K_   9
#define J_   576          // C_*K_
#define EPS_ 1e-5f

// ---------------- scratch (no allocations allowed) ----------------
__device__ float g_xnhwc[B_*HW_*C_];   // x transposed to [B][H][W][C]
__device__ float g_off[B_*HW_*27];     // per pixel: dy[9], dx[9], mask[9]
__device__ float g_wt[J_*O_];          // dcn_w transposed: [j][o]

// ---------------- kernel 0: NCHW -> NHWC transpose ----------------
__global__ void k_transpose(const float* __restrict__ x) {
    __shared__ float t[32][33];
    int xt = blockIdx.x % (W_/32);
    int ct = blockIdx.x / (W_/32);
    int y  = blockIdx.y, b = blockIdx.z;
    int tx = threadIdx.x, ty = threadIdx.y;
#pragma unroll
    for (int i = 0; i < 4; i++) {
        int c  = ct*32 + ty + i*8;
        int xx = xt*32 + tx;
        t[ty + i*8][tx] = x[((b*C_ + c)*H_ + y)*W_ + xx];
    }
    __syncthreads();
#pragma unroll
    for (int i = 0; i < 4; i++) {
        int xx = xt*32 + ty + i*8;
        int c  = ct*32 + tx;
        g_xnhwc[(((b*H_ + y)*W_ + xx) << 6) + c] = t[tx][ty + i*8];
    }
}

// ------ kernel 1: dcn_w -> [j][o] ------
__global__ void k_wprep(const float* __restrict__ dcn_w) {
    int t = blockIdx.x*256 + threadIdx.x;     // t = j*64 + o
    if (t < J_*O_) {
        int o = t & 63;
        int j = t >> 6;
        int c = j & 63;
        int k = j >> 6;
        g_wt[t] = dcn_w[o*J_ + c*K_ + k];
    }
}

// ------- kernel 2: dwconv + BN + ReLU + 1x1 -> offsets / mask -------
__global__ void __launch_bounds__(256) k_offsets(
    const float* __restrict__ dw_w, const float* __restrict__ dw_b,
    const float* __restrict__ bn_g, const float* __restrict__ bn_b,
    const float* __restrict__ bn_m, const float* __restrict__ bn_v,
    const float* __restrict__ pw_w, const float* __restrict__ pw_b)
{
    __shared__ float xt[3*34*64];      // x neighborhood [row 0..2][col 0..33][c]
    __shared__ float hs[32*64];        // h[p][c]
    __shared__ float4 ws[16*27];       // pw_w packed: ws[i4*27+o] = pw_w[o][4*i4..+3]
    __shared__ float pb[27];

    int tid = threadIdx.x;
    int gp0 = blockIdx.x * 32;
    int b   = gp0 / HW_;
    int rem = gp0 % HW_;
    int y   = rem / W_;
    int x0  = rem % W_;

    for (int e4 = tid; e4 < 3*34*16; e4 += 256) {
        int c4 = e4 & 15;
        int t2 = e4 >> 4;
        int xi = t2 % 34;
        int r  = t2 / 34;
        int yy = y - 1 + r;
        int xx = x0 - 1 + xi;
        float4 v = make_float4(0.f, 0.f, 0.f, 0.f);
        if ((unsigned)yy < H_ && (unsigned)xx < W_)
            v = *(const float4*)(g_xnhwc + (((b*H_ + yy)*W_ + xx) << 6) + c4*4);
        ((float4*)xt)[e4] = v;
    }
    for (int e = tid; e < 16*27; e += 256) {
        int o  = e % 27;
        int i4 = e / 27;
        const float* src = pw_w + o*64 + i4*4;
        ws[e] = make_float4(src[0], src[1], src[2], src[3]);
    }
    if (tid < 27) pb[tid] = pw_b[tid];
    __syncthreads();

#pragma unroll
    for (int i = 0; i < 8; i++) {
        int e = tid + i*256;
        int c = e & 63;
        int p = e >> 6;
        float acc = 0.f;
#pragma unroll
        for (int ky = 0; ky < 3; ky++) {
#pragma unroll
            for (int kx = 0; kx < 3; kx++) {
                acc += dw_w[c*9 + ky*3 + kx] * xt[(ky*34 + (p + kx))*64 + c];
            }
        }
        float s = bn_g[c] * rsqrtf(bn_v[c] + EPS_);
        hs[e] = fmaxf((acc + dw_b[c] - bn_m[c]) * s + bn_b[c], 0.f);
    }
    __syncthreads();

    for (int e = tid; e < 32*27; e += 256) {
        int p = e / 27;
        int o = e - p*27;
        float om = pb[o];
        const float4* hv = (const float4*)(hs + p*64);
#pragma unroll
        for (int i4 = 0; i4 < 16; i4++) {
            float4 h4 = hv[i4];
            float4 w4 = ws[i4*27 + o];
            om += h4.x*w4.x + h4.y*w4.y + h4.z*w4.z + h4.w*w4.w;
        }
        float* ob = g_off + (gp0 + p)*27;
        if (o < 18) {
            ob[(o & 1)*9 + (o >> 1)] = om;   // dy slot k / dx slot 9+k
        } else {
            ob[o] = 1.f / (1.f + expf(-om)); // mask slot 18..26
        }
    }
}

// ------- kernel 3: deformable gather + 64x576 projection -------
#define TP  32
#define VSTRIDE 36                           // padded row stride of val_s[j][p]
// smem: val[576][36] + double-buffered W tiles (2 x 2048) + offsets (864)
#define SMEM_FLOATS (J_*VSTRIDE + 2*2048 + 864)
#define SMEM_BYTES  (SMEM_FLOATS*4)

__global__ void __launch_bounds__(256) k_main(float* __restrict__ out) {
    extern __shared__ __align__(16) float sm[];
    float* val_s = sm;                       // [j][p] stride 36
    float* bufA  = sm + J_*VSTRIDE;          // 2048 floats
    float* bufB  = bufA + 2048;              // 2048 floats
    float* off_s = bufB + 2048;              // [p][27]

    int tid  = threadIdx.x;
    int lane = tid & 31;
    int wrp  = tid >> 5;
    int gp0  = blockIdx.x * TP;
    int b    = gp0 / HW_;
    int rem0 = gp0 % HW_;
    int y    = rem0 / W_;                    // one row per block
    int x0   = rem0 % W_;

    // stage this block's offsets once (coalesced)
    for (int e = tid; e < 32*27; e += 256)
        off_s[e] = g_off[gp0*27 + e];

    // prefetch W tile 0 (disjoint smem, no sync needed yet)
    {
        float4* wdst = (float4*)bufA;
        const float4* wsrc = (const float4*)g_wt;
        wdst[tid] = wsrc[tid]; wdst[tid + 256] = wsrc[tid + 256];
    }
    __syncthreads();

    // ---------- gather: warp w -> channels c8=w*8, lane -> pixel ----------
    {
        int c8 = wrp * 8;
        int p  = lane;
        int xx = x0 + p;
        const float* ob = off_s + p*27;
#pragma unroll
        for (int k = 0; k < 9; k++) {
            float dy = ob[k], dx = ob[9+k], m = ob[18+k];
            float py = (float)(y  + k/3 - 1) + dy;
            float px = (float)(xx + k%3 - 1) + dx;
            float fy0 = floorf(py), fx0 = floorf(px);
            float wy1 = py - fy0,   wx1 = px - fx0;
            float wy0 = 1.f - wy1,  wx0 = 1.f - wx1;
            int   iy  = (int)fy0,   ix  = (int)fx0;

            float wts[4] = { wy0*wx0, wy0*wx1, wy1*wx0, wy1*wx1 };
            int   ys[4]  = { iy, iy, iy+1, iy+1 };
            int   xs[4]  = { ix, ix+1, ix, ix+1 };

            float4 a0 = make_float4(0.f,0.f,0.f,0.f);
            float4 a1 = make_float4(0.f,0.f,0.f,0.f);
#pragma unroll
            for (int cn = 0; cn < 4; cn++) {
                if ((unsigned)ys[cn] < H_ && (unsigned)xs[cn] < W_) {
                    const float4* src = (const float4*)
                        (g_xnhwc + (((b*H_ + ys[cn])*W_ + xs[cn]) << 6) + c8);
                    float4 v0 = src[0], v1 = src[1];
                    float w = wts[cn];
                    a0.x += w*v0.x; a0.y += w*v0.y; a0.z += w*v0.z; a0.w += w*v0.w;
                    a1.x += w*v1.x; a1.y += w*v1.y; a1.z += w*v1.z; a1.w += w*v1.w;
                }
            }
            float av[8] = { a0.x*m, a0.y*m, a0.z*m, a0.w*m,
                            a1.x*m, a1.y*m, a1.z*m, a1.w*m };
            float* dst = val_s + (k*64 + c8)*VSTRIDE + p;
#pragma unroll
            for (int i = 0; i < 8; i++) dst[i*VSTRIDE] = av[i];
        }
    }
    __syncthreads();

    // ---------- GEMM: out[p][o] = sum_j val[j][p] * W[j][o] ----------
    int pl = lane >> 2;                      // 0..7 : px group (4 px each)
    int ol = lane & 3;                       // 0..3 : o pair within warp
    int obase = wrp*8 + ol*2;                // this thread's o pair
    const float* vbase = val_s + (pl << 2);

    float a00=0.f, a01=0.f, a10=0.f, a11=0.f;
    float a20=0.f, a21=0.f, a30=0.f, a31=0.f;

#pragma unroll 1
    for (int jt = 0; jt < 18; jt++) {
        const float* cur = (jt & 1) ? bufB : bufA;
        float*       nxt = (jt & 1) ? bufA : bufB;
        if (jt < 17) {
            float4* wdst = (float4*)nxt;
            const float4* wsrc = (const float4*)(g_wt + (jt+1)*2048);
            wdst[tid] = wsrc[tid]; wdst[tid + 256] = wsrc[tid + 256];
        }
        const float* vj = vbase + jt*32*VSTRIDE;
        const float* wj = cur + obase;
#pragma unroll
        for (int jj = 0; jj < 32; jj++) {
            float4 v  = *(const float4*)(vj + jj*VSTRIDE);
            float2 wv = *(const float2*)(wj + jj*64);
            a00 += v.x*wv.x; a01 += v.x*wv.y;
            a10 += v.y*wv.x; a11 += v.y*wv.y;
            a20 += v.z*wv.x; a21 += v.z*wv.y;
            a30 += v.w*wv.x; a31 += v.w*wv.y;
        }
        __syncthreads();
    }

    // stage outputs [o][p] (stride 33), then coalesced store
    float* stg = val_s;                      // val no longer needed
    {
        int px = pl << 2;
        stg[(obase+0)*33 + px+0] = a00; stg[(obase+1)*33 + px+0] = a01;
        stg[(obase+0)*33 + px+1] = a10; stg[(obase+1)*33 + px+1] = a11;
        stg[(obase+0)*33 + px+2] = a20; stg[(obase+1)*33 + px+2] = a21;
        stg[(obase+0)*33 + px+3] = a30; stg[(obase+1)*33 + px+3] = a31;
    }
    __syncthreads();
#pragma unroll
    for (int r = 0; r < 8; r++) {
        int q = r*256 + tid;
        int o = q >> 5;
        int p = q & 31;
        out[(b*O_ + o)*HW_ + rem0 + p] = stg[o*33 + p];
    }
}

// ------- kernel 4: per-(b,o) instance norm + ReLU, in-place -------
__global__ void __launch_bounds__(256) k_inorm(float* __restrict__ out) {
    int bo = blockIdx.x;
    float4* row = (float4*)(out + bo*HW_);
    float s = 0.f, ss = 0.f;
    for (int i = threadIdx.x; i < HW_/4; i += 256) {
        float4 v = row[i];
        s  += v.x + v.y + v.z + v.w;
        ss += v.x*v.x + v.y*v.y + v.z*v.z + v.w*v.w;
    }
#pragma unroll
    for (int off = 16; off; off >>= 1) {
        s  += __shfl_xor_sync(~0u, s,  off);
        ss += __shfl_xor_sync(~0u, ss, off);
    }
    __shared__ float rs[8], rss[8];
    __shared__ float mu_s, rstd_s;
    if ((threadIdx.x & 31) == 0) { rs[threadIdx.x>>5] = s; rss[threadIdx.x>>5] = ss; }
    __syncthreads();
    if (threadIdx.x == 0) {
        float S = 0.f, SS = 0.f;
#pragma unroll
        for (int i = 0; i < 8; i++) { S += rs[i]; SS += rss[i]; }
        float mu  = S / (float)HW_;
        float var = SS / (float)HW_ - mu*mu;
        mu_s = mu;
        rstd_s = rsqrtf(var + EPS_);
    }
    __syncthreads();
    float mu = mu_s, rstd = rstd_s;
    for (int i = threadIdx.x; i < HW_/4; i += 256) {
        float4 v = row[i];
        v.x = fmaxf((v.x - mu)*rstd, 0.f);
        v.y = fmaxf((v.y - mu)*rstd, 0.f);
        v.z = fmaxf((v.z - mu)*rstd, 0.f);
        v.w = fmaxf((v.w - mu)*rstd, 0.f);
        row[i] = v;
    }
}

// ---------------- launch ----------------
extern "C" void kernel_launch(void* const* d_in, const int* in_sizes, int n_in,
                              void* d_out, int out_size) {
    (void)in_sizes; (void)n_in; (void)out_size;
    const float* x     = (const float*)d_in[0];
    const float* dw_w  = (const float*)d_in[1];
    const float* dw_b  = (const float*)d_in[2];
    const float* bn_g  = (const float*)d_in[3];
    const float* bn_b  = (const float*)d_in[4];
    const float* bn_m  = (const float*)d_in[5];
    const float* bn_v  = (const float*)d_in[6];
    const float* pw_w  = (const float*)d_in[7];
    const float* pw_b  = (const float*)d_in[8];
    const float* dcn_w = (const float*)d_in[9];
    // d_in[10] = dcn_b: exactly cancelled by the instance norm -> unused.
    float* out = (float*)d_out;

    cudaFuncSetAttribute(k_main, cudaFuncAttributeMaxDynamicSharedMemorySize, SMEM_BYTES);

    k_transpose<<<dim3((W_/32)*(C_/32), H_, B_), dim3(32, 8)>>>(x);
    k_wprep<<<(J_*O_ + 255)/256, 256>>>(dcn_w);
    k_offsets<<<(B_*HW_)/32, 256>>>(dw_w, dw_b, bn_g, bn_b, bn_m, bn_v, pw_w, pw_b);
    k_main<<<(B_*HW_)/TP, 256, SMEM_BYTES>>>(out);
    k_inorm<<<B_*O_, 256>>>(out);
}

// round 5
// speedup vs baseline: 1.1316x; 1.1316x over previous
#include <cuda_runtime.h>

#define B_   2
#define C_   64
#define H_   192
#define W_   192
#define HW_  (H_*W_)
#define O_   64
#define K_   9
#define J_   576          // C_*K_
#define EPS_ 1e-5f

// ---------------- scratch (no allocations allowed) ----------------
__device__ float g_xnhwc[B_*HW_*C_];   // x transposed to [B][H][W][C]
__device__ float g_off[B_*HW_*27];     // per pixel: dy[9], dx[9], mask[9]
__device__ float g_wt[J_*O_];          // dcn_w paired: [j][32 float2] = (W[j][i], W[j][i+32])

// ---------------- kernel 0: NCHW -> NHWC transpose ----------------
__global__ void k_transpose(const float* __restrict__ x) {
    __shared__ float t[32][33];
    int xt = blockIdx.x % (W_/32);
    int ct = blockIdx.x / (W_/32);
    int y  = blockIdx.y, b = blockIdx.z;
    int tx = threadIdx.x, ty = threadIdx.y;
#pragma unroll
    for (int i = 0; i < 4; i++) {
        int c  = ct*32 + ty + i*8;
        int xx = xt*32 + tx;
        t[ty + i*8][tx] = x[((b*C_ + c)*H_ + y)*W_ + xx];
    }
    __syncthreads();
#pragma unroll
    for (int i = 0; i < 4; i++) {
        int xx = xt*32 + ty + i*8;
        int c  = ct*32 + tx;
        g_xnhwc[(((b*H_ + y)*W_ + xx) << 6) + c] = t[tx][ty + i*8];
    }
}

// ------ kernel 1: dcn_w -> [j][pair(i)] with pair = (o=i, o=i+32) ------
__global__ void k_wprep(const float* __restrict__ dcn_w) {
    int t = blockIdx.x*256 + threadIdx.x;
    if (t < J_*O_) {
        int j    = t >> 6;
        int s    = t & 63;
        int i    = s >> 1;
        int half = s & 1;
        int o    = i + half*32;
        int c    = j & 63;
        int k    = j >> 6;
        g_wt[t] = dcn_w[o*J_ + c*K_ + k];
    }
}

// ------- kernel 2: dwconv + BN + ReLU + 1x1 -> offsets / mask -------
__global__ void __launch_bounds__(256) k_offsets(
    const float* __restrict__ dw_w, const float* __restrict__ dw_b,
    const float* __restrict__ bn_g, const float* __restrict__ bn_b,
    const float* __restrict__ bn_m, const float* __restrict__ bn_v,
    const float* __restrict__ pw_w, const float* __restrict__ pw_b)
{
    __shared__ float xt[3*34*64];
    __shared__ float hs[32*64];
    __shared__ float4 ws[16*27];
    __shared__ float pb[27];

    int tid = threadIdx.x;
    int gp0 = blockIdx.x * 32;
    int b   = gp0 / HW_;
    int rem = gp0 % HW_;
    int y   = rem / W_;
    int x0  = rem % W_;

    for (int e4 = tid; e4 < 3*34*16; e4 += 256) {
        int c4 = e4 & 15;
        int t2 = e4 >> 4;
        int xi = t2 % 34;
        int r  = t2 / 34;
        int yy = y - 1 + r;
        int xx = x0 - 1 + xi;
        float4 v = make_float4(0.f, 0.f, 0.f, 0.f);
        if ((unsigned)yy < H_ && (unsigned)xx < W_)
            v = *(const float4*)(g_xnhwc + (((b*H_ + yy)*W_ + xx) << 6) + c4*4);
        ((float4*)xt)[e4] = v;
    }
    for (int e = tid; e < 16*27; e += 256) {
        int o  = e % 27;
        int i4 = e / 27;
        const float* src = pw_w + o*64 + i4*4;
        ws[e] = make_float4(src[0], src[1], src[2], src[3]);
    }
    if (tid < 27) pb[tid] = pw_b[tid];
    __syncthreads();

#pragma unroll
    for (int i = 0; i < 8; i++) {
        int e = tid + i*256;
        int c = e & 63;
        int p = e >> 6;
        float acc = 0.f;
#pragma unroll
        for (int ky = 0; ky < 3; ky++) {
#pragma unroll
            for (int kx = 0; kx < 3; kx++) {
                acc += dw_w[c*9 + ky*3 + kx] * xt[(ky*34 + (p + kx))*64 + c];
            }
        }
        float s = bn_g[c] * rsqrtf(bn_v[c] + EPS_);
        hs[e] = fmaxf((acc + dw_b[c] - bn_m[c]) * s + bn_b[c], 0.f);
    }
    __syncthreads();

    for (int e = tid; e < 32*27; e += 256) {
        int p = e / 27;
        int o = e - p*27;
        float om = pb[o];
        const float4* hv = (const float4*)(hs + p*64);
#pragma unroll
        for (int i4 = 0; i4 < 16; i4++) {
            float4 h4 = hv[i4];
            float4 w4 = ws[i4*27 + o];
            om += h4.x*w4.x + h4.y*w4.y + h4.z*w4.z + h4.w*w4.w;
        }
        float* ob = g_off + (gp0 + p)*27;
        if (o < 18) {
            ob[(o & 1)*9 + (o >> 1)] = om;   // dy slot k / dx slot 9+k
        } else {
            ob[o] = 1.f / (1.f + expf(-om)); // mask slot 18..26
        }
    }
}

// ------- kernel 3: deformable gather + 64x576 projection -------
#define TP 64
// smem: val[64][576] + double-buffered W tiles (2x2048) + offsets (64*27)
#define SMEM_FLOATS (TP*J_ + 2*2048 + TP*27)
#define SMEM_BYTES  (SMEM_FLOATS*4)

__global__ void __launch_bounds__(256) k_main(float* __restrict__ out) {
    extern __shared__ __align__(16) float sm[];
    float* val_s = sm;                 // [p][j]
    float* bufA  = sm + TP*J_;         // 2048 floats
    float* bufB  = bufA + 2048;        // 2048 floats
    float* off_s = bufB + 2048;        // [p][27]

    int tid  = threadIdx.x;
    int lane = tid & 31;
    int wrp  = tid >> 5;
    int gp0  = blockIdx.x * TP;
    int b    = gp0 / HW_;
    int rem0 = gp0 % HW_;
    int y    = rem0 / W_;              // one row per block (64 | 192)
    int x0   = rem0 % W_;

    // stage offsets + prefetch W tile 0
    for (int e = tid; e < TP*27; e += 256)
        off_s[e] = g_off[gp0*27 + e];
    {
        float4* wdst = (float4*)bufA;
        const float4* wsrc = (const float4*)g_wt;
        wdst[tid] = wsrc[tid]; wdst[tid + 256] = wsrc[tid + 256];
    }
    __syncthreads();

    // ---------- gather: 4 threads per pixel, 16 channels each ----------
    {
        int p   = tid >> 2;            // pixel 0..63
        int c16 = (tid & 3) << 4;      // channel base
        int xx  = x0 + p;
        const float* ob = off_s + p*27;
#pragma unroll
        for (int k = 0; k < 9; k++) {
            float dy = ob[k], dx = ob[9+k], m = ob[18+k];
            float py = (float)(y  + k/3 - 1) + dy;
            float px = (float)(xx + k%3 - 1) + dx;
            float fy0 = floorf(py), fx0 = floorf(px);
            float wy1 = py - fy0,   wx1 = px - fx0;
            float wy0 = 1.f - wy1,  wx0 = 1.f - wx1;
            int   iy  = (int)fy0,   ix  = (int)fx0;

            float wts[4] = { wy0*wx0, wy0*wx1, wy1*wx0, wy1*wx1 };
            int   ys[4]  = { iy, iy, iy+1, iy+1 };
            int   xs[4]  = { ix, ix+1, ix, ix+1 };

            float4 a0 = make_float4(0.f,0.f,0.f,0.f);
            float4 a1 = make_float4(0.f,0.f,0.f,0.f);
            float4 a2 = make_float4(0.f,0.f,0.f,0.f);
            float4 a3 = make_float4(0.f,0.f,0.f,0.f);
#pragma unroll
            for (int cn = 0; cn < 4; cn++) {
                if ((unsigned)ys[cn] < H_ && (unsigned)xs[cn] < W_) {
                    const float4* src = (const float4*)
                        (g_xnhwc + (((b*H_ + ys[cn])*W_ + xs[cn]) << 6) + c16);
                    float4 v0 = src[0], v1 = src[1], v2 = src[2], v3 = src[3];
                    float w = wts[cn];
                    a0.x += w*v0.x; a0.y += w*v0.y; a0.z += w*v0.z; a0.w += w*v0.w;
                    a1.x += w*v1.x; a1.y += w*v1.y; a1.z += w*v1.z; a1.w += w*v1.w;
                    a2.x += w*v2.x; a2.y += w*v2.y; a2.z += w*v2.z; a2.w += w*v2.w;
                    a3.x += w*v3.x; a3.y += w*v3.y; a3.z += w*v3.z; a3.w += w*v3.w;
                }
            }
            a0.x*=m; a0.y*=m; a0.z*=m; a0.w*=m;
            a1.x*=m; a1.y*=m; a1.z*=m; a1.w*=m;
            a2.x*=m; a2.y*=m; a2.z*=m; a2.w*=m;
            a3.x*=m; a3.y*=m; a3.z*=m; a3.w*=m;
            float4* dst = (float4*)(val_s + p*J_ + k*64 + c16);
            dst[0] = a0; dst[1] = a1; dst[2] = a2; dst[3] = a3;
        }
    }
    __syncthreads();

    // ---------- GEMM: out[p][o] = sum_j val[p][j]*W[j][o] ----------
    // warp -> 8 pixels; lane -> o pair (lane, lane+32)
    int p0 = wrp << 3;
    float a0x=0,a0y=0, a1x=0,a1y=0, a2x=0,a2y=0, a3x=0,a3y=0;
    float a4x=0,a4y=0, a5x=0,a5y=0, a6x=0,a6y=0, a7x=0,a7y=0;

    const float* vb0 = val_s + (p0+0)*J_;
    const float* vb1 = val_s + (p0+1)*J_;
    const float* vb2 = val_s + (p0+2)*J_;
    const float* vb3 = val_s + (p0+3)*J_;
    const float* vb4 = val_s + (p0+4)*J_;
    const float* vb5 = val_s + (p0+5)*J_;
    const float* vb6 = val_s + (p0+6)*J_;
    const float* vb7 = val_s + (p0+7)*J_;

#pragma unroll 1
    for (int jt = 0; jt < 18; jt++) {
        const float* cur = (jt & 1) ? bufB : bufA;
        float*       nxt = (jt & 1) ? bufA : bufB;
        if (jt < 17) {
            float4* wdst = (float4*)nxt;
            const float4* wsrc = (const float4*)(g_wt + (jt+1)*2048);
            wdst[tid] = wsrc[tid]; wdst[tid + 256] = wsrc[tid + 256];
        }
        const float2* w2 = (const float2*)cur;
#pragma unroll
        for (int q = 0; q < 8; q++) {
            int jb = jt*32 + q*4;
            float4 v0 = *(const float4*)(vb0 + jb);
            float4 v1 = *(const float4*)(vb1 + jb);
            float4 v2 = *(const float4*)(vb2 + jb);
            float4 v3 = *(const float4*)(vb3 + jb);
            float4 v4 = *(const float4*)(vb4 + jb);
            float4 v5 = *(const float4*)(vb5 + jb);
            float4 v6 = *(const float4*)(vb6 + jb);
            float4 v7 = *(const float4*)(vb7 + jb);
            const float2* wq = w2 + q*128 + lane;
            {   float2 w = wq[0];
                a0x += v0.x*w.x; a0y += v0.x*w.y;  a1x += v1.x*w.x; a1y += v1.x*w.y;
                a2x += v2.x*w.x; a2y += v2.x*w.y;  a3x += v3.x*w.x; a3y += v3.x*w.y;
                a4x += v4.x*w.x; a4y += v4.x*w.y;  a5x += v5.x*w.x; a5y += v5.x*w.y;
                a6x += v6.x*w.x; a6y += v6.x*w.y;  a7x += v7.x*w.x; a7y += v7.x*w.y; }
            {   float2 w = wq[32];
                a0x += v0.y*w.x; a0y += v0.y*w.y;  a1x += v1.y*w.x; a1y += v1.y*w.y;
                a2x += v2.y*w.x; a2y += v2.y*w.y;  a3x += v3.y*w.x; a3y += v3.y*w.y;
                a4x += v4.y*w.x; a4y += v4.y*w.y;  a5x += v5.y*w.x; a5y += v5.y*w.y;
                a6x += v6.y*w.x; a6y += v6.y*w.y;  a7x += v7.y*w.x; a7y += v7.y*w.y; }
            {   float2 w = wq[64];
                a0x += v0.z*w.x; a0y += v0.z*w.y;  a1x += v1.z*w.x; a1y += v1.z*w.y;
                a2x += v2.z*w.x; a2y += v2.z*w.y;  a3x += v3.z*w.x; a3y += v3.z*w.y;
                a4x += v4.z*w.x; a4y += v4.z*w.y;  a5x += v5.z*w.x; a5y += v5.z*w.y;
                a6x += v6.z*w.x; a6y += v6.z*w.y;  a7x += v7.z*w.x; a7y += v7.z*w.y; }
            {   float2 w = wq[96];
                a0x += v0.w*w.x; a0y += v0.w*w.y;  a1x += v1.w*w.x; a1y += v1.w*w.y;
                a2x += v2.w*w.x; a2y += v2.w*w.y;  a3x += v3.w*w.x; a3y += v3.w*w.y;
                a4x += v4.w*w.x; a4y += v4.w*w.y;  a5x += v5.w*w.x; a5y += v5.w*w.y;
                a6x += v6.w*w.x; a6y += v6.w*w.y;  a7x += v7.w*w.x; a7y += v7.w*w.y; }
        }
        __syncthreads();
    }

    // stage outputs [o][p] stride 65 (65 mod 32 = 1 -> conflict-free)
    float* stg = val_s;
    {
        int o0 = lane, o1 = lane + 32;
        stg[o0*65 + p0+0] = a0x; stg[o1*65 + p0+0] = a0y;
        stg[o0*65 + p0+1] = a1x; stg[o1*65 + p0+1] = a1y;
        stg[o0*65 + p0+2] = a2x; stg[o1*65 + p0+2] = a2y;
        stg[o0*65 + p0+3] = a3x; stg[o1*65 + p0+3] = a3y;
        stg[o0*65 + p0+4] = a4x; stg[o1*65 + p0+4] = a4y;
        stg[o0*65 + p0+5] = a5x; stg[o1*65 + p0+5] = a5y;
        stg[o0*65 + p0+6] = a6x; stg[o1*65 + p0+6] = a6y;
        stg[o0*65 + p0+7] = a7x; stg[o1*65 + p0+7] = a7y;
    }
    __syncthreads();
#pragma unroll
    for (int r = 0; r < 16; r++) {
        int q = r*256 + tid;
        int o = q >> 6;
        int p = q & 63;
        out[(b*O_ + o)*HW_ + rem0 + p] = stg[o*65 + p];
    }
}

// ------- kernel 4: per-(b,o) instance norm + ReLU, in-place -------
__global__ void __launch_bounds__(256) k_inorm(float* __restrict__ out) {
    int bo = blockIdx.x;
    float4* row = (float4*)(out + bo*HW_);
    float s = 0.f, ss = 0.f;
    for (int i = threadIdx.x; i < HW_/4; i += 256) {
        float4 v = row[i];
        s  += v.x + v.y + v.z + v.w;
        ss += v.x*v.x + v.y*v.y + v.z*v.z + v.w*v.w;
    }
#pragma unroll
    for (int off = 16; off; off >>= 1) {
        s  += __shfl_xor_sync(~0u, s,  off);
        ss += __shfl_xor_sync(~0u, ss, off);
    }
    __shared__ float rs[8], rss[8];
    __shared__ float mu_s, rstd_s;
    if ((threadIdx.x & 31) == 0) { rs[threadIdx.x>>5] = s; rss[threadIdx.x>>5] = ss; }
    __syncthreads();
    if (threadIdx.x == 0) {
        float S = 0.f, SS = 0.f;
#pragma unroll
        for (int i = 0; i < 8; i++) { S += rs[i]; SS += rss[i]; }
        float mu  = S / (float)HW_;
        float var = SS / (float)HW_ - mu*mu;
        mu_s = mu;
        rstd_s = rsqrtf(var + EPS_);
    }
    __syncthreads();
    float mu = mu_s, rstd = rstd_s;
    for (int i = threadIdx.x; i < HW_/4; i += 256) {
        float4 v = row[i];
        v.x = fmaxf((v.x - mu)*rstd, 0.f);
        v.y = fmaxf((v.y - mu)*rstd, 0.f);
        v.z = fmaxf((v.z - mu)*rstd, 0.f);
        v.w = fmaxf((v.w - mu)*rstd, 0.f);
        row[i] = v;
    }
}

// ---------------- launch ----------------
extern "C" void kernel_launch(void* const* d_in, const int* in_sizes, int n_in,
                              void* d_out, int out_size) {
    (void)in_sizes; (void)n_in; (void)out_size;
    const float* x     = (const float*)d_in[0];
    const float* dw_w  = (const float*)d_in[1];
    const float* dw_b  = (const float*)d_in[2];
    const float* bn_g  = (const float*)d_in[3];
    const float* bn_b  = (const float*)d_in[4];
    const float* bn_m  = (const float*)d_in[5];
    const float* bn_v  = (const float*)d_in[6];
    const float* pw_w  = (const float*)d_in[7];
    const float* pw_b  = (const float*)d_in[8];
    const float* dcn_w = (const float*)d_in[9];
    // d_in[10] = dcn_b: exactly cancelled by the instance norm -> unused.
    float* out = (float*)d_out;

    cudaFuncSetAttribute(k_main, cudaFuncAttributeMaxDynamicSharedMemorySize, SMEM_BYTES);

    k_transpose<<<dim3((W_/32)*(C_/32), H_, B_), dim3(32, 8)>>>(x);
    k_wprep<<<(J_*O_ + 255)/256, 256>>>(dcn_w);
    k_offsets<<<(B_*HW_)/32, 256>>>(dw_w, dw_b, bn_g, bn_b, bn_m, bn_v, pw_w, pw_b);
    k_main<<<(B_*HW_)/TP, 256, SMEM_BYTES>>>(out);
    k_inorm<<<B_*O_, 256>>>(out);
}

// round 6
// speedup vs baseline: 1.3493x; 1.1923x over previous
#include <cuda_runtime.h>

#define B_   2
#define C_   64
#define H_   192
#define W_   192
#define HW_  (H_*W_)
#define NP_  (B_*HW_)
#define O_   64
#define K_   9
#define J_   576
#define EPS_ 1e-5f

// ---------------- scratch (no allocations allowed) ----------------
__device__ float g_xnhwc[B_*HW_*C_];   // x transposed to [B][H][W][C]
__device__ float g_off[27*NP_];        // planar: [slot][pixel]; slot k=dy_k, 9+k=dx_k, 18+k=mask_k
__device__ float g_wt[J_*O_];          // dcn_w transposed: [j][o]

// ---------------- kernel 0: NCHW -> NHWC transpose ----------------
__global__ void k_transpose(const float* __restrict__ x) {
    __shared__ float t[32][33];
    int xt = blockIdx.x % (W_/32);
    int ct = blockIdx.x / (W_/32);
    int y  = blockIdx.y, b = blockIdx.z;
    int tx = threadIdx.x, ty = threadIdx.y;
#pragma unroll
    for (int i = 0; i < 4; i++) {
        int c  = ct*32 + ty + i*8;
        int xx = xt*32 + tx;
        t[ty + i*8][tx] = x[((b*C_ + c)*H_ + y)*W_ + xx];
    }
    __syncthreads();
#pragma unroll
    for (int i = 0; i < 4; i++) {
        int xx = xt*32 + ty + i*8;
        int c  = ct*32 + tx;
        g_xnhwc[(((b*H_ + y)*W_ + xx) << 6) + c] = t[tx][ty + i*8];
    }
}

// ------ kernel 1: dcn_w -> [j][o] ------
__global__ void k_wprep(const float* __restrict__ dcn_w) {
    int t = blockIdx.x*256 + threadIdx.x;     // t = j*64 + o
    if (t < J_*O_) {
        int o = t & 63;
        int j = t >> 6;
        int c = j & 63;
        int k = j >> 6;
        g_wt[t] = dcn_w[o*J_ + c*K_ + k];
    }
}

// ------- kernel 2: dwconv + BN + ReLU + 1x1 -> offsets / mask -------
__global__ void __launch_bounds__(256) k_offsets(
    const float* __restrict__ dw_w, const float* __restrict__ dw_b,
    const float* __restrict__ bn_g, const float* __restrict__ bn_b,
    const float* __restrict__ bn_m, const float* __restrict__ bn_v,
    const float* __restrict__ pw_w, const float* __restrict__ pw_b)
{
    __shared__ float xt[3*34*64];
    __shared__ float hs[32*64];
    __shared__ float4 ws[16*27];
    __shared__ float pb[27];

    int tid = threadIdx.x;
    int gp0 = blockIdx.x * 32;
    int b   = gp0 / HW_;
    int rem = gp0 % HW_;
    int y   = rem / W_;
    int x0  = rem % W_;

    for (int e4 = tid; e4 < 3*34*16; e4 += 256) {
        int c4 = e4 & 15;
        int t2 = e4 >> 4;
        int xi = t2 % 34;
        int r  = t2 / 34;
        int yy = y - 1 + r;
        int xx = x0 - 1 + xi;
        float4 v = make_float4(0.f, 0.f, 0.f, 0.f);
        if ((unsigned)yy < H_ && (unsigned)xx < W_)
            v = *(const float4*)(g_xnhwc + (((b*H_ + yy)*W_ + xx) << 6) + c4*4);
        ((float4*)xt)[e4] = v;
    }
    for (int e = tid; e < 16*27; e += 256) {
        int o  = e % 27;
        int i4 = e / 27;
        const float* src = pw_w + o*64 + i4*4;
        ws[e] = make_float4(src[0], src[1], src[2], src[3]);
    }
    if (tid < 27) pb[tid] = pw_b[tid];
    __syncthreads();

#pragma unroll
    for (int i = 0; i < 8; i++) {
        int e = tid + i*256;
        int c = e & 63;
        int p = e >> 6;
        float acc = 0.f;
#pragma unroll
        for (int ky = 0; ky < 3; ky++) {
#pragma unroll
            for (int kx = 0; kx < 3; kx++) {
                acc += dw_w[c*9 + ky*3 + kx] * xt[(ky*34 + (p + kx))*64 + c];
            }
        }
        float s = bn_g[c] * rsqrtf(bn_v[c] + EPS_);
        hs[e] = fmaxf((acc + dw_b[c] - bn_m[c]) * s + bn_b[c], 0.f);
    }
    __syncthreads();

    for (int e = tid; e < 32*27; e += 256) {
        int p = e / 27;
        int o = e - p*27;
        float om = pb[o];
        const float4* hv = (const float4*)(hs + p*64);
#pragma unroll
        for (int i4 = 0; i4 < 16; i4++) {
            float4 h4 = hv[i4];
            float4 w4 = ws[i4*27 + o];
            om += h4.x*w4.x + h4.y*w4.y + h4.z*w4.z + h4.w*w4.w;
        }
        int slot;
        float v;
        if (o < 18) { slot = (o & 1)*9 + (o >> 1); v = om; }
        else        { slot = o; v = 1.f / (1.f + expf(-om)); }
        g_off[slot*NP_ + gp0 + p] = v;
    }
}

// ------- kernel 3: deformable gather + 64x576 projection -------
// 256 px x 64 o per block; K processed in 9 chunks of 64 (one tap k each).
#define VST 260                               // val_T row stride (260 % 32 = 4)
#define SMEM_FLOATS (64*VST + 64*64)          // val_T[64][260] + W chunk [64][64]
#define SMEM_BYTES  (SMEM_FLOATS*4)

__global__ void __launch_bounds__(256, 2) k_main(float* __restrict__ out) {
    extern __shared__ __align__(16) float sm[];
    float* val_T = sm;                        // [c][p], stride VST
    float* w_s   = sm + 64*VST;               // [c][o], stride 64

    int tid  = threadIdx.x;
    int lane = tid & 31;
    int warp = tid >> 5;
    int gp0  = blockIdx.x * 256;
    int b    = gp0 / HW_;
    int rem0 = gp0 % HW_;
    int gp   = gp0 + tid;
    int rem  = rem0 + tid;
    int y0   = rem / W_;
    int x0   = rem % W_;

    // accumulators: px = h*128 + lane*4 + i ; o = warp*8 + oo
    float acc[2][4][8];
#pragma unroll
    for (int h = 0; h < 2; h++)
#pragma unroll
        for (int i = 0; i < 4; i++)
#pragma unroll
            for (int oo = 0; oo < 8; oo++) acc[h][i][oo] = 0.f;

#pragma unroll 1
    for (int k = 0; k < 9; k++) {
        if (k) __syncthreads();               // previous GEMM done with val_T/w_s

        // ---- load W chunk [64][64] (16 KB, coalesced) ----
        {
            const float4* wsrc = (const float4*)(g_wt + k*64*64);
            float4* wdst = (float4*)w_s;
#pragma unroll
            for (int r = 0; r < 4; r++) wdst[tid + r*256] = wsrc[tid + r*256];
        }

        // ---- gather this tap: thread = pixel, 64 channels ----
        {
            float dy = g_off[k*NP_ + gp];
            float dx = g_off[(9+k)*NP_ + gp];
            float m  = g_off[(18+k)*NP_ + gp];
            float py = (float)(y0 + k/3 - 1) + dy;
            float px = (float)(x0 + k%3 - 1) + dx;
            float fy0 = floorf(py), fx0 = floorf(px);
            float wy1 = py - fy0,   wx1 = px - fx0;
            float wy0 = 1.f - wy1,  wx0 = 1.f - wx1;
            int   iy  = (int)fy0,   ix  = (int)fx0;

            float wts[4] = { wy0*wx0*m, wy0*wx1*m, wy1*wx0*m, wy1*wx1*m };
            int   ys[4]  = { iy, iy, iy+1, iy+1 };
            int   xs[4]  = { ix, ix+1, ix, ix+1 };
            const float* bp[4];
#pragma unroll
            for (int cn = 0; cn < 4; cn++) {
                bool v = (unsigned)ys[cn] < H_ && (unsigned)xs[cn] < W_;
                wts[cn] = v ? wts[cn] : 0.f;
                bp[cn]  = v ? g_xnhwc + (((b*H_ + ys[cn])*W_ + xs[cn]) << 6)
                            : g_xnhwc;
            }
#pragma unroll
            for (int cg = 0; cg < 16; cg++) {
                float4 c0 = *(const float4*)(bp[0] + cg*4);
                float4 c1 = *(const float4*)(bp[1] + cg*4);
                float4 c2 = *(const float4*)(bp[2] + cg*4);
                float4 c3 = *(const float4*)(bp[3] + cg*4);
                float4 a;
                a.x = wts[0]*c0.x + wts[1]*c1.x + wts[2]*c2.x + wts[3]*c3.x;
                a.y = wts[0]*c0.y + wts[1]*c1.y + wts[2]*c2.y + wts[3]*c3.y;
                a.z = wts[0]*c0.z + wts[1]*c1.z + wts[2]*c2.z + wts[3]*c3.z;
                a.w = wts[0]*c0.w + wts[1]*c1.w + wts[2]*c2.w + wts[3]*c3.w;
                val_T[(cg*4+0)*VST + tid] = a.x;
                val_T[(cg*4+1)*VST + tid] = a.y;
                val_T[(cg*4+2)*VST + tid] = a.z;
                val_T[(cg*4+3)*VST + tid] = a.w;
            }
        }
        __syncthreads();

        // ---- GEMM chunk: acc += val_T[c][px] * w_s[c][o] ----
#pragma unroll 2
        for (int c = 0; c < 64; c++) {
            float4 v0 = *(const float4*)(val_T + c*VST + lane*4);
            float4 v1 = *(const float4*)(val_T + c*VST + 128 + lane*4);
            float4 w0 = *(const float4*)(w_s + c*64 + warp*8);
            float4 w1 = *(const float4*)(w_s + c*64 + warp*8 + 4);
            float vv0[4] = { v0.x, v0.y, v0.z, v0.w };
            float vv1[4] = { v1.x, v1.y, v1.z, v1.w };
            float ww[8]  = { w0.x, w0.y, w0.z, w0.w, w1.x, w1.y, w1.z, w1.w };
#pragma unroll
            for (int i = 0; i < 4; i++)
#pragma unroll
                for (int oo = 0; oo < 8; oo++) {
                    acc[0][i][oo] += vv0[i] * ww[oo];
                    acc[1][i][oo] += vv1[i] * ww[oo];
                }
        }
    }

    // ---- epilogue: stage [o][p] in val_T, then coalesced NCHW store ----
    __syncthreads();
#pragma unroll
    for (int oo = 0; oo < 8; oo++) {
        int o = warp*8 + oo;
        *(float4*)(val_T + o*VST + lane*4) =
            make_float4(acc[0][0][oo], acc[0][1][oo], acc[0][2][oo], acc[0][3][oo]);
        *(float4*)(val_T + o*VST + 128 + lane*4) =
            make_float4(acc[1][0][oo], acc[1][1][oo], acc[1][2][oo], acc[1][3][oo]);
    }
    __syncthreads();
#pragma unroll 1
    for (int o = 0; o < 64; o++)
        out[(b*O_ + o)*HW_ + rem0 + tid] = val_T[o*VST + tid];
}

// ------- kernel 4: per-(b,o) instance norm + ReLU, in-place -------
__global__ void __launch_bounds__(256) k_inorm(float* __restrict__ out) {
    int bo = blockIdx.x;
    float4* row = (float4*)(out + bo*HW_);
    float s = 0.f, ss = 0.f;
    for (int i = threadIdx.x; i < HW_/4; i += 256) {
        float4 v = row[i];
        s  += v.x + v.y + v.z + v.w;
        ss += v.x*v.x + v.y*v.y + v.z*v.z + v.w*v.w;
    }
#pragma unroll
    for (int off = 16; off; off >>= 1) {
        s  += __shfl_xor_sync(~0u, s,  off);
        ss += __shfl_xor_sync(~0u, ss, off);
    }
    __shared__ float rs[8], rss[8];
    __shared__ float mu_s, rstd_s;
    if ((threadIdx.x & 31) == 0) { rs[threadIdx.x>>5] = s; rss[threadIdx.x>>5] = ss; }
    __syncthreads();
    if (threadIdx.x == 0) {
        float S = 0.f, SS = 0.f;
#pragma unroll
        for (int i = 0; i < 8; i++) { S += rs[i]; SS += rss[i]; }
        float mu  = S / (float)HW_;
        float var = SS / (float)HW_ - mu*mu;
        mu_s = mu;
        rstd_s = rsqrtf(var + EPS_);
    }
    __syncthreads();
    float mu = mu_s, rstd = rstd_s;
    for (int i = threadIdx.x; i < HW_/4; i += 256) {
        float4 v = row[i];
        v.x = fmaxf((v.x - mu)*rstd, 0.f);
        v.y = fmaxf((v.y - mu)*rstd, 0.f);
        v.z = fmaxf((v.z - mu)*rstd, 0.f);
        v.w = fmaxf((v.w - mu)*rstd, 0.f);
        row[i] = v;
    }
}

// ---------------- launch ----------------
extern "C" void kernel_launch(void* const* d_in, const int* in_sizes, int n_in,
                              void* d_out, int out_size) {
    (void)in_sizes; (void)n_in; (void)out_size;
    const float* x     = (const float*)d_in[0];
    const float* dw_w  = (const float*)d_in[1];
    const float* dw_b  = (const float*)d_in[2];
    const float* bn_g  = (const float*)d_in[3];
    const float* bn_b  = (const float*)d_in[4];
    const float* bn_m  = (const float*)d_in[5];
    const float* bn_v  = (const float*)d_in[6];
    const float* pw_w  = (const float*)d_in[7];
    const float* pw_b  = (const float*)d_in[8];
    const float* dcn_w = (const float*)d_in[9];
    // d_in[10] = dcn_b: exactly cancelled by the instance norm -> unused.
    float* out = (float*)d_out;

    cudaFuncSetAttribute(k_main, cudaFuncAttributeMaxDynamicSharedMemorySize, SMEM_BYTES);

    k_transpose<<<dim3((W_/32)*(C_/32), H_, B_), dim3(32, 8)>>>(x);
    k_wprep<<<(J_*O_ + 255)/256, 256>>>(dcn_w);
    k_offsets<<<(B_*HW_)/32, 256>>>(dw_w, dw_b, bn_g, bn_b, bn_m, bn_v, pw_w, pw_b);
    k_main<<<NP_/256, 256, SMEM_BYTES>>>(out);
    k_inorm<<<B_*O_, 256>>>(out);
}

// round 8
// speedup vs baseline: 1.5826x; 1.1729x over previous
#include <cuda_runtime.h>

#define B_   2
#define C_   64
#define H_   192
#define W_   192
#define HW_  (H_*W_)
#define NP_  (B_*HW_)
#define O_   64
#define K_   9
#define J_   576
#define EPS_ 1e-5f

// ---------------- scratch (no allocations allowed) ----------------
__device__ float g_xnhwc[B_*HW_*C_];   // x transposed to [B][H][W][C]
__device__ float g_off[27*NP_];        // planar: [slot][pixel]
__device__ float g_wt[J_*O_];          // dcn_w transposed: [j][o]

// ---------------- kernel 0: NCHW -> NHWC transpose ----------------
__global__ void k_transpose(const float* __restrict__ x) {
    __shared__ float t[32][33];
    int xt = blockIdx.x % (W_/32);
    int ct = blockIdx.x / (W_/32);
    int y  = blockIdx.y, b = blockIdx.z;
    int tx = threadIdx.x, ty = threadIdx.y;
#pragma unroll
    for (int i = 0; i < 4; i++) {
        int c  = ct*32 + ty + i*8;
        int xx = xt*32 + tx;
        t[ty + i*8][tx] = x[((b*C_ + c)*H_ + y)*W_ + xx];
    }
    __syncthreads();
#pragma unroll
    for (int i = 0; i < 4; i++) {
        int xx = xt*32 + ty + i*8;
        int c  = ct*32 + tx;
        g_xnhwc[(((b*H_ + y)*W_ + xx) << 6) + c] = t[tx][ty + i*8];
    }
}

// ------ kernel 1: dcn_w -> [j][o] ------
__global__ void k_wprep(const float* __restrict__ dcn_w) {
    int t = blockIdx.x*256 + threadIdx.x;     // t = j*64 + o
    if (t < J_*O_) {
        int o = t & 63;
        int j = t >> 6;
        int c = j & 63;
        int k = j >> 6;
        g_wt[t] = dcn_w[o*J_ + c*K_ + k];
    }
}

// ------- kernel 2: dwconv + BN + ReLU + 1x1 -> offsets / mask -------
__global__ void __launch_bounds__(256) k_offsets(
    const float* __restrict__ dw_w, const float* __restrict__ dw_b,
    const float* __restrict__ bn_g, const float* __restrict__ bn_b,
    const float* __restrict__ bn_m, const float* __restrict__ bn_v,
    const float* __restrict__ pw_w, const float* __restrict__ pw_b)
{
    __shared__ float xt[3*34*64];
    __shared__ float hs[32*64];
    __shared__ float4 ws[16*27];
    __shared__ float pb[27];

    int tid = threadIdx.x;
    int gp0 = blockIdx.x * 32;
    int b   = gp0 / HW_;
    int rem = gp0 % HW_;
    int y   = rem / W_;
    int x0  = rem % W_;

    for (int e4 = tid; e4 < 3*34*16; e4 += 256) {
        int c4 = e4 & 15;
        int t2 = e4 >> 4;
        int xi = t2 % 34;
        int r  = t2 / 34;
        int yy = y - 1 + r;
        int xx = x0 - 1 + xi;
        float4 v = make_float4(0.f, 0.f, 0.f, 0.f);
        if ((unsigned)yy < H_ && (unsigned)xx < W_)
            v = *(const float4*)(g_xnhwc + (((b*H_ + yy)*W_ + xx) << 6) + c4*4);
        ((float4*)xt)[e4] = v;
    }
    for (int e = tid; e < 16*27; e += 256) {
        int o  = e % 27;
        int i4 = e / 27;
        const float* src = pw_w + o*64 + i4*4;
        ws[e] = make_float4(src[0], src[1], src[2], src[3]);
    }
    if (tid < 27) pb[tid] = pw_b[tid];
    __syncthreads();

#pragma unroll
    for (int i = 0; i < 8; i++) {
        int e = tid + i*256;
        int c = e & 63;
        int p = e >> 6;
        float acc = 0.f;
#pragma unroll
        for (int ky = 0; ky < 3; ky++) {
#pragma unroll
            for (int kx = 0; kx < 3; kx++) {
                acc += dw_w[c*9 + ky*3 + kx] * xt[(ky*34 + (p + kx))*64 + c];
            }
        }
        float s = bn_g[c] * rsqrtf(bn_v[c] + EPS_);
        hs[e] = fmaxf((acc + dw_b[c] - bn_m[c]) * s + bn_b[c], 0.f);
    }
    __syncthreads();

    for (int e = tid; e < 32*27; e += 256) {
        int p = e / 27;
        int o = e - p*27;
        float om = pb[o];
        const float4* hv = (const float4*)(hs + p*64);
#pragma unroll
        for (int i4 = 0; i4 < 16; i4++) {
            float4 h4 = hv[i4];
            float4 w4 = ws[i4*27 + o];
            om += h4.x*w4.x + h4.y*w4.y + h4.z*w4.z + h4.w*w4.w;
        }
        int slot;
        float v;
        if (o < 18) { slot = (o & 1)*9 + (o >> 1); v = om; }
        else        { slot = o; v = 1.f / (1.f + expf(-om)); }
        g_off[slot*NP_ + gp0 + p] = v;
    }
}

// ------- kernel 3: deformable gather + 64x576 projection -------
// 256 px x 64 o per block; K in 9 chunks of 64 (one tap each).
// val_T element (c,p) at c*VST + SHIFT(c) + p, SHIFT(c)=4*((c>>2)&7).
#define VST 292
#define SHIFT_ROW(c) ((((c) >> 2) & 7) * 4)
#define SMEM_FLOATS (64*VST + 64*64)
#define SMEM_BYTES  (SMEM_FLOATS*4)

__global__ void __launch_bounds__(256, 2) k_main(float* __restrict__ out) {
    extern __shared__ __align__(16) float sm[];
    float* val_T = sm;                        // [c][p], stride VST, swizzled
    float* w_s   = sm + 64*VST;               // [c][o], stride 64

    int tid  = threadIdx.x;
    int lane = tid & 31;
    int warp = tid >> 5;
    int gp0  = blockIdx.x * 256;
    int b    = gp0 / HW_;
    int rem0 = gp0 % HW_;

    int c4 = tid & 15;                        // channel quad (gather role)
    int pi = tid >> 4;                        // pixel sub-index 0..15
    int sh = (c4 & 7) * 4;                    // store column shift for rows 4*c4+u

    // accumulators: px = h*128 + lane*4 + i ; o = warp*8 + oo
    float acc[2][4][8];
#pragma unroll
    for (int h = 0; h < 2; h++)
#pragma unroll
        for (int i = 0; i < 4; i++)
#pragma unroll
            for (int oo = 0; oo < 8; oo++) acc[h][i][oo] = 0.f;

#pragma unroll 1
    for (int k = 0; k < 9; k++) {
        if (k) __syncthreads();               // previous GEMM done with val_T/w_s

        // ---- load W chunk [64][64] (16 KB, coalesced) ----
        {
            const float4* wsrc = (const float4*)(g_wt + k*64*64);
            float4* wdst = (float4*)w_s;
#pragma unroll
            for (int r = 0; r < 4; r++) wdst[tid + r*256] = wsrc[tid + r*256];
        }

        // ---- gather this tap: 16 lanes per pixel (one float4 each) ----
        int ky = k/3 - 1, kx = k%3 - 1;
#pragma unroll 1
        for (int it = 0; it < 16; it++) {
            int p   = it*16 + pi;
            int gp  = gp0 + p;
            int rem = rem0 + p;
            int y0  = rem / W_;
            int x0  = rem - y0*W_;

            float dy = g_off[k*NP_ + gp];
            float dx = g_off[(9+k)*NP_ + gp];
            float m  = g_off[(18+k)*NP_ + gp];
            float py = (float)(y0 + ky) + dy;
            float px = (float)(x0 + kx) + dx;
            float fy0 = floorf(py), fx0 = floorf(px);
            float wy1 = py - fy0,   wx1 = px - fx0;
            float wy0 = 1.f - wy1,  wx0 = 1.f - wx1;
            int   iy  = (int)fy0,   ix  = (int)fx0;

            float wts[4] = { wy0*wx0*m, wy0*wx1*m, wy1*wx0*m, wy1*wx1*m };
            int   ys[4]  = { iy, iy, iy+1, iy+1 };
            int   xs[4]  = { ix, ix+1, ix, ix+1 };

            float ax = 0.f, ay = 0.f, az = 0.f, aw = 0.f;
#pragma unroll
            for (int cn = 0; cn < 4; cn++) {
                bool v = (unsigned)ys[cn] < H_ && (unsigned)xs[cn] < W_;
                float wv = v ? wts[cn] : 0.f;
                const float* bp = v ? g_xnhwc + (((b*H_ + ys[cn])*W_ + xs[cn]) << 6)
                                    : g_xnhwc;
                float4 c = *(const float4*)(bp + c4*4);
                ax += wv*c.x; ay += wv*c.y; az += wv*c.z; aw += wv*c.w;
            }
            float* dst = val_T + (c4*4)*VST + sh + p;
            dst[0*VST] = ax;
            dst[1*VST] = ay;
            dst[2*VST] = az;
            dst[3*VST] = aw;
        }
        __syncthreads();

        // ---- GEMM chunk: acc += val_T[c][px] * w_s[c][o] ----
#pragma unroll 2
        for (int c = 0; c < 64; c++) {
            const float* vrow = val_T + c*VST + SHIFT_ROW(c);
            float4 v0 = *(const float4*)(vrow + lane*4);
            float4 v1 = *(const float4*)(vrow + 128 + lane*4);
            float4 w0 = *(const float4*)(w_s + c*64 + warp*8);
            float4 w1 = *(const float4*)(w_s + c*64 + warp*8 + 4);
            float vv0[4] = { v0.x, v0.y, v0.z, v0.w };
            float vv1[4] = { v1.x, v1.y, v1.z, v1.w };
            float ww[8]  = { w0.x, w0.y, w0.z, w0.w, w1.x, w1.y, w1.z, w1.w };
#pragma unroll
            for (int i = 0; i < 4; i++)
#pragma unroll
                for (int oo = 0; oo < 8; oo++) {
                    acc[0][i][oo] += vv0[i] * ww[oo];
                    acc[1][i][oo] += vv1[i] * ww[oo];
                }
        }
    }

    // ---- epilogue: stage [o][p] in val_T (plain layout), coalesced store ----
    __syncthreads();
#pragma unroll
    for (int oo = 0; oo < 8; oo++) {
        int o = warp*8 + oo;
        *(float4*)(val_T + o*VST + lane*4) =
            make_float4(acc[0][0][oo], acc[0][1][oo], acc[0][2][oo], acc[0][3][oo]);
        *(float4*)(val_T + o*VST + 128 + lane*4) =
            make_float4(acc[1][0][oo], acc[1][1][oo], acc[1][2][oo], acc[1][3][oo]);
    }
    __syncthreads();
#pragma unroll 1
    for (int o = 0; o < 64; o++)
        out[(b*O_ + o)*HW_ + rem0 + tid] = val_T[o*VST + tid];
}

// ------- kernel 4: per-(b,o) instance norm + ReLU, in-place -------
__global__ void __launch_bounds__(256) k_inorm(float* __restrict__ out) {
    int bo = blockIdx.x;
    float4* row = (float4*)(out + bo*HW_);
    float s = 0.f, ss = 0.f;
    for (int i = threadIdx.x; i < HW_/4; i += 256) {
        float4 v = row[i];
        s  += v.x + v.y + v.z + v.w;
        ss += v.x*v.x + v.y*v.y + v.z*v.z + v.w*v.w;
    }
#pragma unroll
    for (int off = 16; off; off >>= 1) {
        s  += __shfl_xor_sync(~0u, s,  off);
        ss += __shfl_xor_sync(~0u, ss, off);
    }
    __shared__ float rs[8], rss[8];
    __shared__ float mu_s, rstd_s;
    if ((threadIdx.x & 31) == 0) { rs[threadIdx.x>>5] = s; rss[threadIdx.x>>5] = ss; }
    __syncthreads();
    if (threadIdx.x == 0) {
        float S = 0.f, SS = 0.f;
#pragma unroll
        for (int i = 0; i < 8; i++) { S += rs[i]; SS += rss[i]; }
        float mu  = S / (float)HW_;
        float var = SS / (float)HW_ - mu*mu;
        mu_s = mu;
        rstd_s = rsqrtf(var + EPS_);
    }
    __syncthreads();
    float mu = mu_s, rstd = rstd_s;
    for (int i = threadIdx.x; i < HW_/4; i += 256) {
        float4 v = row[i];
        v.x = fmaxf((v.x - mu)*rstd, 0.f);
        v.y = fmaxf((v.y - mu)*rstd, 0.f);
        v.z = fmaxf((v.z - mu)*rstd, 0.f);
        v.w = fmaxf((v.w - mu)*rstd, 0.f);
        row[i] = v;
    }
}

// ---------------- launch ----------------
extern "C" void kernel_launch(void* const* d_in, const int* in_sizes, int n_in,
                              void* d_out, int out_size) {
    (void)in_sizes; (void)n_in; (void)out_size;
    const float* x     = (const float*)d_in[0];
    const float* dw_w  = (const float*)d_in[1];
    const float* dw_b  = (const float*)d_in[2];
    const float* bn_g  = (const float*)d_in[3];
    const float* bn_b  = (const float*)d_in[4];
    const float* bn_m  = (const float*)d_in[5];
    const float* bn_v  = (const float*)d_in[6];
    const float* pw_w  = (const float*)d_in[7];
    const float* pw_b  = (const float*)d_in[8];
    const float* dcn_w = (const float*)d_in[9];
    // d_in[10] = dcn_b: exactly cancelled by the instance norm -> unused.
    float* out = (float*)d_out;

    cudaFuncSetAttribute(k_main, cudaFuncAttributeMaxDynamicSharedMemorySize, SMEM_BYTES);

    k_transpose<<<dim3((W_/32)*(C_/32), H_, B_), dim3(32, 8)>>>(x);
    k_wprep<<<(J_*O_ + 255)/256, 256>>>(dcn_w);
    k_offsets<<<(B_*HW_)/32, 256>>>(dw_w, dw_b, bn_g, bn_b, bn_m, bn_v, pw_w, pw_b);
    k_main<<<NP_/256, 256, SMEM_BYTES>>>(out);
    k_inorm<<<B_*O_, 256>>>(out);
}

// round 11
// speedup vs baseline: 1.7762x; 1.1224x over previous
#include <cuda_runtime.h>
#include <cstdint>

#define B_   2
#define C_   64
#define H_   192
#define W_   192
#define HW_  (H_*W_)
#define NP_  (B_*HW_)
#define O_   64
#define K_   9
#define J_   576
#define EPS_ 1e-5f

// ---------------- scratch (no allocations allowed) ----------------
__device__ float g_xnhwc[B_*HW_*C_];   // x transposed to [B][H][W][C]
__device__ float g_off[27*NP_];        // planar: [slot][pixel]
__device__ float g_wt[J_*O_];          // dcn_w transposed: [j][o]

// tf32 conversion: destination must be a .b32 register
__device__ __forceinline__ uint32_t tf32_hi(float v) {
    uint32_t r;
    asm("cvt.rna.tf32.f32 %0, %1;" : "=r"(r) : "f"(v));
    return r;
}
__device__ __forceinline__ void mma_tf32(float* c, const uint32_t* a, uint32_t b0, uint32_t b1) {
    asm volatile(
        "mma.sync.aligned.m16n8k8.row.col.f32.tf32.tf32.f32 "
        "{%0,%1,%2,%3}, {%4,%5,%6,%7}, {%8,%9}, {%0,%1,%2,%3};"
        : "+f"(c[0]), "+f"(c[1]), "+f"(c[2]), "+f"(c[3])
        : "r"(a[0]), "r"(a[1]), "r"(a[2]), "r"(a[3]),
          "r"(b0),  "r"(b1));
}

// ---------------- kernel 0: NCHW -> NHWC transpose ----------------
__global__ void k_transpose(const float* __restrict__ x) {
    __shared__ float t[32][33];
    int xt = blockIdx.x % (W_/32);
    int ct = blockIdx.x / (W_/32);
    int y  = blockIdx.y, b = blockIdx.z;
    int tx = threadIdx.x, ty = threadIdx.y;
#pragma unroll
    for (int i = 0; i < 4; i++) {
        int c  = ct*32 + ty + i*8;
        int xx = xt*32 + tx;
        t[ty + i*8][tx] = x[((b*C_ + c)*H_ + y)*W_ + xx];
    }
    __syncthreads();
#pragma unroll
    for (int i = 0; i < 4; i++) {
        int xx = xt*32 + ty + i*8;
        int c  = ct*32 + tx;
        g_xnhwc[(((b*H_ + y)*W_ + xx) << 6) + c] = t[tx][ty + i*8];
    }
}

// ------ kernel 1: dcn_w -> [j][o] ------
__global__ void k_wprep(const float* __restrict__ dcn_w) {
    int t = blockIdx.x*256 + threadIdx.x;     // t = j*64 + o
    if (t < J_*O_) {
        int o = t & 63;
        int j = t >> 6;
        int c = j & 63;
        int k = j >> 6;
        g_wt[t] = dcn_w[o*J_ + c*K_ + k];
    }
}

// ------- kernel 2: dwconv + BN + ReLU + 1x1 -> offsets / mask -------
__global__ void __launch_bounds__(256) k_offsets(
    const float* __restrict__ dw_w, const float* __restrict__ dw_b,
    const float* __restrict__ bn_g, const float* __restrict__ bn_b,
    const float* __restrict__ bn_m, const float* __restrict__ bn_v,
    const float* __restrict__ pw_w, const float* __restrict__ pw_b)
{
    __shared__ float xt[3*34*64];
    __shared__ float hs[32*64];
    __shared__ float4 ws[16*27];
    __shared__ float pb[27];

    int tid = threadIdx.x;
    int gp0 = blockIdx.x * 32;
    int b   = gp0 / HW_;
    int rem = gp0 % HW_;
    int y   = rem / W_;
    int x0  = rem % W_;

    for (int e4 = tid; e4 < 3*34*16; e4 += 256) {
        int c4 = e4 & 15;
        int t2 = e4 >> 4;
        int xi = t2 % 34;
        int r  = t2 / 34;
        int yy = y - 1 + r;
        int xx = x0 - 1 + xi;
        float4 v = make_float4(0.f, 0.f, 0.f, 0.f);
        if ((unsigned)yy < H_ && (unsigned)xx < W_)
            v = *(const float4*)(g_xnhwc + (((b*H_ + yy)*W_ + xx) << 6) + c4*4);
        ((float4*)xt)[e4] = v;
    }
    for (int e = tid; e < 16*27; e += 256) {
        int o  = e % 27;
        int i4 = e / 27;
        const float* src = pw_w + o*64 + i4*4;
        ws[e] = make_float4(src[0], src[1], src[2], src[3]);
    }
    if (tid < 27) pb[tid] = pw_b[tid];
    __syncthreads();

#pragma unroll
    for (int i = 0; i < 8; i++) {
        int e = tid + i*256;
        int c = e & 63;
        int p = e >> 6;
        float acc = 0.f;
#pragma unroll
        for (int ky = 0; ky < 3; ky++) {
#pragma unroll
            for (int kx = 0; kx < 3; kx++) {
                acc += dw_w[c*9 + ky*3 + kx] * xt[(ky*34 + (p + kx))*64 + c];
            }
        }
        float s = bn_g[c] * rsqrtf(bn_v[c] + EPS_);
        hs[e] = fmaxf((acc + dw_b[c] - bn_m[c]) * s + bn_b[c], 0.f);
    }
    __syncthreads();

    for (int e = tid; e < 32*27; e += 256) {
        int p = e / 27;
        int o = e - p*27;
        float om = pb[o];
        const float4* hv = (const float4*)(hs + p*64);
#pragma unroll
        for (int i4 = 0; i4 < 16; i4++) {
            float4 h4 = hv[i4];
            float4 w4 = ws[i4*27 + o];
            om += h4.x*w4.x + h4.y*w4.y + h4.z*w4.z + h4.w*w4.w;
        }
        int slot;
        float v;
        if (o < 18) { slot = (o & 1)*9 + (o >> 1); v = om; }
        else        { slot = o; v = 1.f / (1.f + expf(-om)); }
        g_off[slot*NP_ + gp0 + p] = v;
    }
}

// ------- kernel 3: deformable gather + tf32 mma projection -------
// 256 px x 64 o per block, 9 taps of K=64. 3xTF32 split in registers.
#define AST 68                                   // val_s row stride
#define WST 72                                   // w_s row stride
#define SMEM_FLOATS (256*AST + 64*WST)
#define SMEM_BYTES  (SMEM_FLOATS*4)

__global__ void __launch_bounds__(256, 2) k_main(float* __restrict__ out) {
    extern __shared__ __align__(16) float sm[];
    float* val_s = sm;                           // [p][c], stride AST
    float* w_s   = sm + 256*AST;                 // [c][o], stride WST

    int tid  = threadIdx.x;
    int lane = tid & 31;
    int warp = tid >> 5;
    int g    = lane >> 2;                        // fragment group 0..7
    int t    = lane & 3;                         // thread-in-group 0..3
    int gp0  = blockIdx.x * 256;
    int b    = gp0 / HW_;
    int rem0 = gp0 % HW_;

    int c4 = tid & 15;                           // gather: channel quad
    int pi = tid >> 4;                           // gather: pixel sub-index

    float acc[2][8][4];
#pragma unroll
    for (int mi = 0; mi < 2; mi++)
#pragma unroll
        for (int ni = 0; ni < 8; ni++)
#pragma unroll
            for (int r = 0; r < 4; r++) acc[mi][ni][r] = 0.f;

#pragma unroll 1
    for (int k = 0; k < 9; k++) {
        if (k) __syncthreads();                  // prev GEMM done with val_s/w_s

        // ---- load W chunk [64][64] into w_s (stride 72) ----
        for (int e = tid; e < 64*16; e += 256) {
            int row  = e >> 4;
            int quad = e & 15;
            *(float4*)(w_s + row*WST + quad*4) =
                *(const float4*)(g_wt + k*4096 + row*64 + quad*4);
        }

        // ---- gather this tap: 16 lanes per pixel (one float4 each) ----
        int ky = k/3 - 1, kx = k%3 - 1;
#pragma unroll 1
        for (int it = 0; it < 16; it++) {
            int p   = it*16 + pi;
            int gp  = gp0 + p;
            int rem = rem0 + p;
            int y0  = rem / W_;
            int x0  = rem - y0*W_;

            float dy = g_off[k*NP_ + gp];
            float dx = g_off[(9+k)*NP_ + gp];
            float m  = g_off[(18+k)*NP_ + gp];
            float py = (float)(y0 + ky) + dy;
            float px = (float)(x0 + kx) + dx;
            float fy0 = floorf(py), fx0 = floorf(px);
            float wy1 = py - fy0,   wx1 = px - fx0;
            float wy0 = 1.f - wy1,  wx0 = 1.f - wx1;
            int   iy  = (int)fy0,   ix  = (int)fx0;

            float wts[4] = { wy0*wx0*m, wy0*wx1*m, wy1*wx0*m, wy1*wx1*m };
            int   ys[4]  = { iy, iy, iy+1, iy+1 };
            int   xs[4]  = { ix, ix+1, ix, ix+1 };

            float ax = 0.f, ay = 0.f, az = 0.f, aw = 0.f;
#pragma unroll
            for (int cn = 0; cn < 4; cn++) {
                bool v = (unsigned)ys[cn] < H_ && (unsigned)xs[cn] < W_;
                float wv = v ? wts[cn] : 0.f;
                const float* bp = v ? g_xnhwc + (((b*H_ + ys[cn])*W_ + xs[cn]) << 6)
                                    : g_xnhwc;
                float4 c = *(const float4*)(bp + c4*4);
                ax += wv*c.x; ay += wv*c.y; az += wv*c.z; aw += wv*c.w;
            }
            *(float4*)(val_s + p*AST + c4*4) = make_float4(ax, ay, az, aw);
        }
        __syncthreads();

        // ---- GEMM chunk via mma.sync tf32 (3-pass split) ----
#pragma unroll
        for (int kq = 0; kq < 8; kq++) {
            int c0 = kq*8;
            uint32_t ahi[2][4], alo[2][4];
#pragma unroll
            for (int mi = 0; mi < 2; mi++) {
                int r0 = warp*32 + mi*16 + g;
                float v0 = val_s[r0*AST       + c0 + t];
                float v1 = val_s[(r0+8)*AST   + c0 + t];
                float v2 = val_s[r0*AST       + c0 + t + 4];
                float v3 = val_s[(r0+8)*AST   + c0 + t + 4];
                ahi[mi][0] = tf32_hi(v0); alo[mi][0] = tf32_hi(v0 - __uint_as_float(ahi[mi][0]));
                ahi[mi][1] = tf32_hi(v1); alo[mi][1] = tf32_hi(v1 - __uint_as_float(ahi[mi][1]));
                ahi[mi][2] = tf32_hi(v2); alo[mi][2] = tf32_hi(v2 - __uint_as_float(ahi[mi][2]));
                ahi[mi][3] = tf32_hi(v3); alo[mi][3] = tf32_hi(v3 - __uint_as_float(ahi[mi][3]));
            }
#pragma unroll
            for (int ni = 0; ni < 8; ni++) {
                float w0 = w_s[(c0+t)*WST   + ni*8 + g];
                float w1 = w_s[(c0+t+4)*WST + ni*8 + g];
                uint32_t bh0 = tf32_hi(w0), bl0 = tf32_hi(w0 - __uint_as_float(bh0));
                uint32_t bh1 = tf32_hi(w1), bl1 = tf32_hi(w1 - __uint_as_float(bh1));
                mma_tf32(acc[0][ni], ahi[0], bh0, bh1);
                mma_tf32(acc[1][ni], ahi[1], bh0, bh1);
                mma_tf32(acc[0][ni], ahi[0], bl0, bl1);
                mma_tf32(acc[1][ni], ahi[1], bl0, bl1);
                mma_tf32(acc[0][ni], alo[0], bh0, bh1);
                mma_tf32(acc[1][ni], alo[1], bh0, bh1);
            }
        }
    }

    // ---- epilogue: stage [o][p] (stride 260), coalesced NCHW store ----
    __syncthreads();
    float* stg = val_s;                          // 64*260 = 16640 <= 256*68
#pragma unroll
    for (int mi = 0; mi < 2; mi++)
#pragma unroll
        for (int ni = 0; ni < 8; ni++) {
            int o = ni*8 + 2*t;
            int r = warp*32 + mi*16 + g;
            stg[o*260 + r]         = acc[mi][ni][0];
            stg[(o+1)*260 + r]     = acc[mi][ni][1];
            stg[o*260 + r + 8]     = acc[mi][ni][2];
            stg[(o+1)*260 + r + 8] = acc[mi][ni][3];
        }
    __syncthreads();
#pragma unroll 1
    for (int o = 0; o < 64; o++)
        out[(b*O_ + o)*HW_ + rem0 + tid] = stg[o*260 + tid];
}

// ------- kernel 4: per-(b,o) instance norm + ReLU, in-place -------
__global__ void __launch_bounds__(256) k_inorm(float* __restrict__ out) {
    int bo = blockIdx.x;
    float4* row = (float4*)(out + bo*HW_);
    float s = 0.f, ss = 0.f;
    for (int i = threadIdx.x; i < HW_/4; i += 256) {
        float4 v = row[i];
        s  += v.x + v.y + v.z + v.w;
        ss += v.x*v.x + v.y*v.y + v.z*v.z + v.w*v.w;
    }
#pragma unroll
    for (int off = 16; off; off >>= 1) {
        s  += __shfl_xor_sync(~0u, s,  off);
        ss += __shfl_xor_sync(~0u, ss, off);
    }
    __shared__ float rs[8], rss[8];
    __shared__ float mu_s, rstd_s;
    if ((threadIdx.x & 31) == 0) { rs[threadIdx.x>>5] = s; rss[threadIdx.x>>5] = ss; }
    __syncthreads();
    if (threadIdx.x == 0) {
        float S = 0.f, SS = 0.f;
#pragma unroll
        for (int i = 0; i < 8; i++) { S += rs[i]; SS += rss[i]; }
        float mu  = S / (float)HW_;
        float var = SS / (float)HW_ - mu*mu;
        mu_s = mu;
        rstd_s = rsqrtf(var + EPS_);
    }
    __syncthreads();
    float mu = mu_s, rstd = rstd_s;
    for (int i = threadIdx.x; i < HW_/4; i += 256) {
        float4 v = row[i];
        v.x = fmaxf((v.x - mu)*rstd, 0.f);
        v.y = fmaxf((v.y - mu)*rstd, 0.f);
        v.z = fmaxf((v.z - mu)*rstd, 0.f);
        v.w = fmaxf((v.w - mu)*rstd, 0.f);
        row[i] = v;
    }
}

// ---------------- launch ----------------
extern "C" void kernel_launch(void* const* d_in, const int* in_sizes, int n_in,
                              void* d_out, int out_size) {
    (void)in_sizes; (void)n_in; (void)out_size;
    const float* x     = (const float*)d_in[0];
    const float* dw_w  = (const float*)d_in[1];
    const float* dw_b  = (const float*)d_in[2];
    const float* bn_g  = (const float*)d_in[3];
    const float* bn_b  = (const float*)d_in[4];
    const float* bn_m  = (const float*)d_in[5];
    const float* bn_v  = (const float*)d_in[6];
    const float* pw_w  = (const float*)d_in[7];
    const float* pw_b  = (const float*)d_in[8];
    const float* dcn_w = (const float*)d_in[9];
    // d_in[10] = dcn_b: exactly cancelled by the instance norm -> unused.
    float* out = (float*)d_out;

    cudaFuncSetAttribute(k_main, cudaFuncAttributeMaxDynamicSharedMemorySize, SMEM_BYTES);

    k_transpose<<<dim3((W_/32)*(C_/32), H_, B_), dim3(32, 8)>>>(x);
    k_wprep<<<(J_*O_ + 255)/256, 256>>>(dcn_w);
    k_offsets<<<(B_*HW_)/32, 256>>>(dw_w, dw_b, bn_g, bn_b, bn_m, bn_v, pw_w, pw_b);
    k_main<<<NP_/256, 256, SMEM_BYTES>>>(out);
    k_inorm<<<B_*O_, 256>>>(out);
}

// round 12
// speedup vs baseline: 1.8471x; 1.0399x over previous
#include <cuda_runtime.h>
#include <cstdint>

#define B_   2
#define C_   64
#define H_   192
#define W_   192
#define HW_  (H_*W_)
#define NP_  (B_*HW_)
#define O_   64
#define K_   9
#define J_   576
#define EPS_ 1e-5f

// ---------------- scratch (no allocations allowed) ----------------
__device__ float    g_xnhwc[B_*HW_*C_];  // x transposed to [B][H][W][C]
__device__ float    g_off[27*NP_];       // planar: [slot][pixel]
__device__ uint32_t g_wt_hi[J_*O_];      // dcn_w transposed [j][o], tf32 hi
__device__ uint32_t g_wt_lo[J_*O_];      // tf32(lo residual)

// tf32 conversion: destination must be a .b32 register
__device__ __forceinline__ uint32_t tf32_hi(float v) {
    uint32_t r;
    asm("cvt.rna.tf32.f32 %0, %1;" : "=r"(r) : "f"(v));
    return r;
}
__device__ __forceinline__ void mma_tf32(float* c, const uint32_t* a, uint32_t b0, uint32_t b1) {
    asm volatile(
        "mma.sync.aligned.m16n8k8.row.col.f32.tf32.tf32.f32 "
        "{%0,%1,%2,%3}, {%4,%5,%6,%7}, {%8,%9}, {%0,%1,%2,%3};"
        : "+f"(c[0]), "+f"(c[1]), "+f"(c[2]), "+f"(c[3])
        : "r"(a[0]), "r"(a[1]), "r"(a[2]), "r"(a[3]),
          "r"(b0),  "r"(b1));
}

// ---------------- kernel 0: NCHW -> NHWC transpose ----------------
__global__ void k_transpose(const float* __restrict__ x) {
    __shared__ float t[32][33];
    int xt = blockIdx.x % (W_/32);
    int ct = blockIdx.x / (W_/32);
    int y  = blockIdx.y, b = blockIdx.z;
    int tx = threadIdx.x, ty = threadIdx.y;
#pragma unroll
    for (int i = 0; i < 4; i++) {
        int c  = ct*32 + ty + i*8;
        int xx = xt*32 + tx;
        t[ty + i*8][tx] = x[((b*C_ + c)*H_ + y)*W_ + xx];
    }
    __syncthreads();
#pragma unroll
    for (int i = 0; i < 4; i++) {
        int xx = xt*32 + ty + i*8;
        int c  = ct*32 + tx;
        g_xnhwc[(((b*H_ + y)*W_ + xx) << 6) + c] = t[tx][ty + i*8];
    }
}

// ------ kernel 1: dcn_w -> [j][o], pre-split into tf32 hi/lo ------
__global__ void k_wprep(const float* __restrict__ dcn_w) {
    int t = blockIdx.x*256 + threadIdx.x;     // t = j*64 + o
    if (t < J_*O_) {
        int o = t & 63;
        int j = t >> 6;
        int c = j & 63;
        int k = j >> 6;
        float v = dcn_w[o*J_ + c*K_ + k];
        uint32_t hi = tf32_hi(v);
        g_wt_hi[t] = hi;
        g_wt_lo[t] = tf32_hi(v - __uint_as_float(hi));
    }
}

// ------- kernel 2: dwconv + BN + ReLU + 1x1 -> offsets / mask -------
__global__ void __launch_bounds__(256) k_offsets(
    const float* __restrict__ dw_w, const float* __restrict__ dw_b,
    const float* __restrict__ bn_g, const float* __restrict__ bn_b,
    const float* __restrict__ bn_m, const float* __restrict__ bn_v,
    const float* __restrict__ pw_w, const float* __restrict__ pw_b)
{
    __shared__ float xt[3*34*64];
    __shared__ float hs[32*64];
    __shared__ float4 ws[16*27];
    __shared__ float pb[27];

    int tid = threadIdx.x;
    int gp0 = blockIdx.x * 32;
    int b   = gp0 / HW_;
    int rem = gp0 % HW_;
    int y   = rem / W_;
    int x0  = rem % W_;

    for (int e4 = tid; e4 < 3*34*16; e4 += 256) {
        int c4 = e4 & 15;
        int t2 = e4 >> 4;
        int xi = t2 % 34;
        int r  = t2 / 34;
        int yy = y - 1 + r;
        int xx = x0 - 1 + xi;
        float4 v = make_float4(0.f, 0.f, 0.f, 0.f);
        if ((unsigned)yy < H_ && (unsigned)xx < W_)
            v = *(const float4*)(g_xnhwc + (((b*H_ + yy)*W_ + xx) << 6) + c4*4);
        ((float4*)xt)[e4] = v;
    }
    for (int e = tid; e < 16*27; e += 256) {
        int o  = e % 27;
        int i4 = e / 27;
        const float* src = pw_w + o*64 + i4*4;
        ws[e] = make_float4(src[0], src[1], src[2], src[3]);
    }
    if (tid < 27) pb[tid] = pw_b[tid];
    __syncthreads();

#pragma unroll
    for (int i = 0; i < 8; i++) {
        int e = tid + i*256;
        int c = e & 63;
        int p = e >> 6;
        float acc = 0.f;
#pragma unroll
        for (int ky = 0; ky < 3; ky++) {
#pragma unroll
            for (int kx = 0; kx < 3; kx++) {
                acc += dw_w[c*9 + ky*3 + kx] * xt[(ky*34 + (p + kx))*64 + c];
            }
        }
        float s = bn_g[c] * rsqrtf(bn_v[c] + EPS_);
        hs[e] = fmaxf((acc + dw_b[c] - bn_m[c]) * s + bn_b[c], 0.f);
    }
    __syncthreads();

    for (int e = tid; e < 32*27; e += 256) {
        int p = e / 27;
        int o = e - p*27;
        float om = pb[o];
        const float4* hv = (const float4*)(hs + p*64);
#pragma unroll
        for (int i4 = 0; i4 < 16; i4++) {
            float4 h4 = hv[i4];
            float4 w4 = ws[i4*27 + o];
            om += h4.x*w4.x + h4.y*w4.y + h4.z*w4.z + h4.w*w4.w;
        }
        int slot;
        float v;
        if (o < 18) { slot = (o & 1)*9 + (o >> 1); v = om; }
        else        { slot = o; v = 1.f / (1.f + expf(-om)); }
        g_off[slot*NP_ + gp0 + p] = v;
    }
}

// ------- kernel 3: deformable gather + tf32 mma projection -------
// 256 px x 64 o per block, 9 taps of K=64. 3xTF32 split; W pre-split in gmem.
#define AST 68                                   // val_s row stride
#define WST 72                                   // w tile row stride
#define SMEM_FLOATS (256*AST + 2*64*WST)
#define SMEM_BYTES  (SMEM_FLOATS*4)

__global__ void __launch_bounds__(256, 2) k_main(float* __restrict__ out) {
    extern __shared__ __align__(16) float sm[];
    float*    val_s = sm;                        // [p][c], stride AST
    uint32_t* wh_s  = (uint32_t*)(sm + 256*AST);           // [c][o] hi
    uint32_t* wl_s  = (uint32_t*)(sm + 256*AST + 64*WST);  // [c][o] lo

    int tid  = threadIdx.x;
    int lane = tid & 31;
    int warp = tid >> 5;
    int g    = lane >> 2;                        // fragment group 0..7
    int t    = lane & 3;                         // thread-in-group 0..3
    int gp0  = blockIdx.x * 256;
    int b    = gp0 / HW_;
    int rem0 = gp0 % HW_;

    int c4 = tid & 15;                           // gather: channel quad
    int pi = tid >> 4;                           // gather: pixel sub-index

    float acc[2][8][4];
#pragma unroll
    for (int mi = 0; mi < 2; mi++)
#pragma unroll
        for (int ni = 0; ni < 8; ni++)
#pragma unroll
            for (int r = 0; r < 4; r++) acc[mi][ni][r] = 0.f;

#pragma unroll 1
    for (int k = 0; k < 9; k++) {
        if (k) __syncthreads();                  // prev GEMM done with smem

        // ---- load W hi/lo chunks [64][64] (stride 72) ----
        for (int e = tid; e < 64*16; e += 256) {
            int row  = e >> 4;
            int quad = e & 15;
            *(uint4*)(wh_s + row*WST + quad*4) =
                *(const uint4*)(g_wt_hi + k*4096 + row*64 + quad*4);
            *(uint4*)(wl_s + row*WST + quad*4) =
                *(const uint4*)(g_wt_lo + k*4096 + row*64 + quad*4);
        }

        // ---- gather this tap: 16 lanes per pixel (one float4 each) ----
        int ky = k/3 - 1, kx = k%3 - 1;
#pragma unroll 1
        for (int it = 0; it < 16; it++) {
            int p   = it*16 + pi;
            int gp  = gp0 + p;
            int rem = rem0 + p;
            int y0  = rem / W_;
            int x0  = rem - y0*W_;

            float dy = g_off[k*NP_ + gp];
            float dx = g_off[(9+k)*NP_ + gp];
            float m  = g_off[(18+k)*NP_ + gp];
            float py = (float)(y0 + ky) + dy;
            float px = (float)(x0 + kx) + dx;
            float fy0 = floorf(py), fx0 = floorf(px);
            float wy1 = py - fy0,   wx1 = px - fx0;
            float wy0 = 1.f - wy1,  wx0 = 1.f - wx1;
            int   iy  = (int)fy0,   ix  = (int)fx0;

            float wts[4] = { wy0*wx0*m, wy0*wx1*m, wy1*wx0*m, wy1*wx1*m };
            int   ys[4]  = { iy, iy, iy+1, iy+1 };
            int   xs[4]  = { ix, ix+1, ix, ix+1 };

            float ax = 0.f, ay = 0.f, az = 0.f, aw = 0.f;
#pragma unroll
            for (int cn = 0; cn < 4; cn++) {
                bool v = (unsigned)ys[cn] < H_ && (unsigned)xs[cn] < W_;
                float wv = v ? wts[cn] : 0.f;
                const float* bp = v ? g_xnhwc + (((b*H_ + ys[cn])*W_ + xs[cn]) << 6)
                                    : g_xnhwc;
                float4 c = *(const float4*)(bp + c4*4);
                ax += wv*c.x; ay += wv*c.y; az += wv*c.z; aw += wv*c.w;
            }
            *(float4*)(val_s + p*AST + c4*4) = make_float4(ax, ay, az, aw);
        }
        __syncthreads();

        // ---- GEMM chunk via mma.sync tf32 (3-pass split) ----
#pragma unroll
        for (int kq = 0; kq < 8; kq++) {
            int c0 = kq*8;
            uint32_t ahi[2][4], alo[2][4];
#pragma unroll
            for (int mi = 0; mi < 2; mi++) {
                int r0 = warp*32 + mi*16 + g;
                float v0 = val_s[r0*AST       + c0 + t];
                float v1 = val_s[(r0+8)*AST   + c0 + t];
                float v2 = val_s[r0*AST       + c0 + t + 4];
                float v3 = val_s[(r0+8)*AST   + c0 + t + 4];
                ahi[mi][0] = tf32_hi(v0); alo[mi][0] = tf32_hi(v0 - __uint_as_float(ahi[mi][0]));
                ahi[mi][1] = tf32_hi(v1); alo[mi][1] = tf32_hi(v1 - __uint_as_float(ahi[mi][1]));
                ahi[mi][2] = tf32_hi(v2); alo[mi][2] = tf32_hi(v2 - __uint_as_float(ahi[mi][2]));
                ahi[mi][3] = tf32_hi(v3); alo[mi][3] = tf32_hi(v3 - __uint_as_float(ahi[mi][3]));
            }
#pragma unroll
            for (int ni = 0; ni < 8; ni++) {
                uint32_t bh0 = wh_s[(c0+t)*WST   + ni*8 + g];
                uint32_t bh1 = wh_s[(c0+t+4)*WST + ni*8 + g];
                uint32_t bl0 = wl_s[(c0+t)*WST   + ni*8 + g];
                uint32_t bl1 = wl_s[(c0+t+4)*WST + ni*8 + g];
                mma_tf32(acc[0][ni], ahi[0], bh0, bh1);
                mma_tf32(acc[1][ni], ahi[1], bh0, bh1);
                mma_tf32(acc[0][ni], ahi[0], bl0, bl1);
                mma_tf32(acc[1][ni], ahi[1], bl0, bl1);
                mma_tf32(acc[0][ni], alo[0], bh0, bh1);
                mma_tf32(acc[1][ni], alo[1], bh0, bh1);
            }
        }
    }

    // ---- epilogue: stage [o][p] (stride 260), coalesced NCHW store ----
    __syncthreads();
    float* stg = val_s;                          // 64*260 = 16640 <= 256*68
#pragma unroll
    for (int mi = 0; mi < 2; mi++)
#pragma unroll
        for (int ni = 0; ni < 8; ni++) {
            int o = ni*8 + 2*t;
            int r = warp*32 + mi*16 + g;
            stg[o*260 + r]         = acc[mi][ni][0];
            stg[(o+1)*260 + r]     = acc[mi][ni][1];
            stg[o*260 + r + 8]     = acc[mi][ni][2];
            stg[(o+1)*260 + r + 8] = acc[mi][ni][3];
        }
    __syncthreads();
#pragma unroll 1
    for (int o = 0; o < 64; o++)
        out[(b*O_ + o)*HW_ + rem0 + tid] = stg[o*260 + tid];
}

// ------- kernel 4: per-(b,o) instance norm + ReLU, in-place -------
__global__ void __launch_bounds__(256) k_inorm(float* __restrict__ out) {
    int bo = blockIdx.x;
    float4* row = (float4*)(out + bo*HW_);
    float s = 0.f, ss = 0.f;
    for (int i = threadIdx.x; i < HW_/4; i += 256) {
        float4 v = row[i];
        s  += v.x + v.y + v.z + v.w;
        ss += v.x*v.x + v.y*v.y + v.z*v.z + v.w*v.w;
    }
#pragma unroll
    for (int off = 16; off; off >>= 1) {
        s  += __shfl_xor_sync(~0u, s,  off);
        ss += __shfl_xor_sync(~0u, ss, off);
    }
    __shared__ float rs[8], rss[8];
    __shared__ float mu_s, rstd_s;
    if ((threadIdx.x & 31) == 0) { rs[threadIdx.x>>5] = s; rss[threadIdx.x>>5] = ss; }
    __syncthreads();
    if (threadIdx.x == 0) {
        float S = 0.f, SS = 0.f;
#pragma unroll
        for (int i = 0; i < 8; i++) { S += rs[i]; SS += rss[i]; }
        float mu  = S / (float)HW_;
        float var = SS / (float)HW_ - mu*mu;
        mu_s = mu;
        rstd_s = rsqrtf(var + EPS_);
    }
    __syncthreads();
    float mu = mu_s, rstd = rstd_s;
    for (int i = threadIdx.x; i < HW_/4; i += 256) {
        float4 v = row[i];
        v.x = fmaxf((v.x - mu)*rstd, 0.f);
        v.y = fmaxf((v.y - mu)*rstd, 0.f);
        v.z = fmaxf((v.z - mu)*rstd, 0.f);
        v.w = fmaxf((v.w - mu)*rstd, 0.f);
        row[i] = v;
    }
}

// ---------------- launch ----------------
extern "C" void kernel_launch(void* const* d_in, const int* in_sizes, int n_in,
                              void* d_out, int out_size) {
    (void)in_sizes; (void)n_in; (void)out_size;
    const float* x     = (const float*)d_in[0];
    const float* dw_w  = (const float*)d_in[1];
    const float* dw_b  = (const float*)d_in[2];
    const float* bn_g  = (const float*)d_in[3];
    const float* bn_b  = (const float*)d_in[4];
    const float* bn_m  = (const float*)d_in[5];
    const float* bn_v  = (const float*)d_in[6];
    const float* pw_w  = (const float*)d_in[7];
    const float* pw_b  = (const float*)d_in[8];
    const float* dcn_w = (const float*)d_in[9];
    // d_in[10] = dcn_b: exactly cancelled by the instance norm -> unused.
    float* out = (float*)d_out;

    cudaFuncSetAttribute(k_main, cudaFuncAttributeMaxDynamicSharedMemorySize, SMEM_BYTES);

    k_transpose<<<dim3((W_/32)*(C_/32), H_, B_), dim3(32, 8)>>>(x);
    k_wprep<<<(J_*O_ + 255)/256, 256>>>(dcn_w);
    k_offsets<<<(B_*HW_)/32, 256>>>(dw_w, dw_b, bn_g, bn_b, bn_m, bn_v, pw_w, pw_b);
    k_main<<<NP_/256, 256, SMEM_BYTES>>>(out);
    k_inorm<<<B_*O_, 256>>>(out);
}